// round 6
// baseline (speedup 1.0000x reference)
#include <cuda_runtime.h>

// Problem constants (fixed by the dataset): B=256, T=512, K=128
#define Bn 256
#define Tn 512
#define Kn 128

// Device scratch (no allocs allowed).
__device__ float g_partial[Bn];
__device__ int   g_perm[Bn];   // g_perm[rank] = batch index, by seq_len
__device__ int   g_done;       // zero-init; last CTA resets to 0 each run

// ---- packed f32x2 helpers (sm_103a) ---------------------------------------
__device__ __forceinline__ unsigned long long fma2(unsigned long long a,
                                                   unsigned long long b,
                                                   unsigned long long c) {
    unsigned long long d;
    asm("fma.rn.f32x2 %0, %1, %2, %3;" : "=l"(d) : "l"(a), "l"(b), "l"(c));
    return d;
}
__device__ __forceinline__ unsigned long long add2(unsigned long long a,
                                                   unsigned long long b) {
    unsigned long long d;
    asm("add.rn.f32x2 %0, %1, %2;" : "=l"(d) : "l"(a), "l"(b));
    return d;
}
__device__ __forceinline__ unsigned long long pack2(float lo, float hi) {
    unsigned long long d;
    asm("mov.b64 %0, {%1, %2};" : "=l"(d) : "f"(lo), "f"(hi));
    return d;
}
__device__ __forceinline__ float2 unpack2(unsigned long long v) {
    float lo, hi;
    asm("mov.b64 {%0, %1}, %2;" : "=f"(lo), "=f"(hi) : "l"(v));
    return make_float2(lo, hi);
}

// ---- scheduler: grid=32 x 256 threads; warp w ranks batch 8*bx+w ----------
__global__ void crf_sched_kernel(const int* __restrict__ seq_lens)
{
    const int lane = threadIdx.x & 31;
    const int i    = blockIdx.x * 8 + (threadIdx.x >> 5);
    const int Li   = seq_lens[i];
    int r = 0;
    #pragma unroll
    for (int kk = 0; kk < 8; kk++) {
        int k  = lane + 32 * kk;
        int Lk = seq_lens[k];
        r += (Lk < Li) || (Lk == Li && k < i);   // unique ranks
    }
    #pragma unroll
    for (int o = 16; o; o >>= 1) r += __shfl_xor_sync(0xffffffffu, r, o);
    if (lane == 0) g_perm[r] = i;
}

// One scan step. Assumes previous step's barrier has been passed; publishes
// next beta into sh_beta[cur^1] and flips cur. RENORM steps rescale by the
// stale beta[0] (exact LSE shift; only overflow cares, bounded << e^88).
#define CRF_STEP(LO, RENORM) do {                                            \
    const float* bp_ = sh_beta[cur];                                         \
    float cj_;                                                               \
    if (RENORM) {                                                            \
        float rr_ = bp_[0];                                                  \
        float lr_ = __logf(rr_);                                             \
        S += lr_;                                                            \
        cj_ = __expf((LO) - lr_);                                            \
    } else {                                                                 \
        cj_ = __expf(LO);                                                    \
    }                                                                        \
    const double2* ap_ = (const double2*)(bp_ + 68 * h);                     \
    unsigned long long a0_ = 0ull, a1_ = 0ull, a2_ = 0ull, a3_ = 0ull;       \
    _Pragma("unroll")                                                        \
    for (int k_ = 0; k_ < 8; k_++) {                                         \
        double2 x_ = ap_[2 * k_];            /* LDS.128 2-addr broadcast */  \
        double2 y_ = ap_[2 * k_ + 1];                                        \
        a0_ = fma2(__double_as_longlong(x_.x), eT2[4 * k_ + 0], a0_);        \
        a1_ = fma2(__double_as_longlong(x_.y), eT2[4 * k_ + 1], a1_);        \
        a2_ = fma2(__double_as_longlong(y_.x), eT2[4 * k_ + 2], a2_);        \
        a3_ = fma2(__double_as_longlong(y_.y), eT2[4 * k_ + 3], a3_);        \
    }                                                                        \
    unsigned long long aa_ = add2(add2(a0_, a1_), add2(a2_, a3_));           \
    float2 pp_ = unpack2(aa_);                                               \
    float  sv_ = pp_.x + pp_.y;                                              \
    sv_ += __shfl_xor_sync(0xffffffffu, sv_, 1);   /* combine halves */      \
    float nb_ = sv_ * cj_;                                                   \
    if (!h) sh_beta[cur ^ 1][slotj] = nb_;                                   \
    __syncthreads();                         /* the ONLY barrier per step */ \
    cur ^= 1;                                                                \
} while (0)

// grid=128 CTAs, 256 threads, one CTA/SM. CTA c runs batches perm[c] then
// perm[255-c] (length-balanced pairs). Thread tau: column j=tau>>1, half
// h=tau&1 owns i in [64h,64h+64) as 32 packed f32x2 registers. Linear-domain
// scan, renorm every 4 steps, 8x unrolled with static prefetch registers.
__global__ __launch_bounds__(256, 1) void crf_forward_kernel(
    const float* __restrict__ logits,   // [B, T, K]
    const int*   __restrict__ labels,   // [B, T]
    const int*   __restrict__ seq_lens, // [B]
    const float* __restrict__ trans,    // [K, K] trans[i*K + j]
    float* __restrict__ out)
{
    __shared__ __align__(16) float sh_beta[2][136]; // half0 @0, half1 @68
    __shared__ float sh_wred[8];
    __shared__ int   sh_last;

    const int c    = blockIdx.x;         // 0..127
    const int tau  = threadIdx.x;        // 0..255
    const int j    = tau >> 1;           // column 0..127
    const int h    = tau & 1;            // half
    const int lane = tau & 31;
    const int warp = tau >> 5;
    const int slotj = (j < 64) ? j : j + 4;

    // batch indices for this CTA (issue loads early, hide behind eT2 exps)
    const int bA = g_perm[c];
    const int bB = g_perm[Bn - 1 - c];

    // expT rows [64h, 64h+64) of column j, packed over row-pairs
    unsigned long long eT2[32];
    #pragma unroll
    for (int k = 0; k < 32; k++) {
        float e0 = __expf(trans[(64 * h + 2 * k)     * Kn + j]);
        float e1 = __expf(trans[(64 * h + 2 * k + 1) * Kn + j]);
        eT2[k] = pack2(e0, e1);
    }

    for (int p = 0; p < 2; p++) {
        const int b = p ? bB : bA;
        const int    Tlen = seq_lens[b];                  // 1..512
        const float* lg   = logits + (size_t)b * Tn * Kn;
        const int*   lb   = labels + b * Tn;

        // ---------- gold-path score: unary + pairwise ----------
        float sc = 0.f;
        for (int t = tau; t < Tlen; t += 256) {
            int y = lb[t];
            sc += lg[t * Kn + y];
            if (t >= 1) sc += trans[lb[t - 1] * Kn + y];
        }
        #pragma unroll
        for (int o = 16; o; o >>= 1) sc += __shfl_xor_sync(0xffffffffu, sc, o);
        if (lane == 0) sh_wred[warp] = sc;

        // beta_0 = exp(logits[b,0,:]), S = 0
        if (!h) sh_beta[0][slotj] = __expf(lg[j]);

        // static prefetch registers: rows 1..8 (always in-bounds, Tn=512)
        float la0 = lg[1 * Kn + j], la1 = lg[2 * Kn + j];
        float la2 = lg[3 * Kn + j], la3 = lg[4 * Kn + j];
        float lb0 = lg[5 * Kn + j], lb1 = lg[6 * Kn + j];
        float lb2 = lg[7 * Kn + j], lb3 = lg[8 * Kn + j];

        __syncthreads();
        float score = 0.f;
        #pragma unroll
        for (int w = 0; w < 8; w++) score += sh_wred[w];

        // ---------- forward recursion, 8x unrolled ----------
        float S   = 0.f;
        int   cur = 0;
        int   t   = 1;
        #define ROW(tt) lg[(((tt) < Tn - 1) ? (tt) : (Tn - 1)) * Kn + j]
        while (t + 7 < Tlen) {
            CRF_STEP(la0, true);  la0 = ROW(t + 8);
            CRF_STEP(la1, false); la1 = ROW(t + 9);
            CRF_STEP(la2, false); la2 = ROW(t + 10);
            CRF_STEP(la3, false); la3 = ROW(t + 11);
            CRF_STEP(lb0, true);  lb0 = ROW(t + 12);
            CRF_STEP(lb1, false); lb1 = ROW(t + 13);
            CRF_STEP(lb2, false); lb2 = ROW(t + 14);
            CRF_STEP(lb3, false); lb3 = ROW(t + 15);
            t += 8;
        }
        #undef ROW
        // remainder <= 7 steps; la/lb hold rows t..t+6 (Tlen uniform -> safe)
        if (t     < Tlen) CRF_STEP(la0, true);
        if (t + 1 < Tlen) CRF_STEP(la1, false);
        if (t + 2 < Tlen) CRF_STEP(la2, false);
        if (t + 3 < Tlen) CRF_STEP(la3, false);
        if (t + 4 < Tlen) CRF_STEP(lb0, true);
        if (t + 5 < Tlen) CRF_STEP(lb1, false);
        if (t + 6 < Tlen) CRF_STEP(lb2, false);

        // ---------- log_z = S + log(sum_j beta_j) ----------
        __syncthreads();                         // protect sh_wred reuse
        float v = 0.f;
        if (tau < Kn) v = sh_beta[cur][(tau < 64) ? tau : tau + 4];
        #pragma unroll
        for (int o = 16; o; o >>= 1) v += __shfl_xor_sync(0xffffffffu, v, o);
        if (lane == 0) sh_wred[warp] = v;
        __syncthreads();

        if (tau == 0) {
            float stot = ((sh_wred[0] + sh_wred[1]) + (sh_wred[2] + sh_wred[3]))
                       + ((sh_wred[4] + sh_wred[5]) + (sh_wred[6] + sh_wred[7]));
            g_partial[b] = S + __logf(stot) - score;   // per-batch NLL
        }
        __syncthreads();                         // smem safe for next batch
    }

    // ---------- fused final reduction: last CTA sums deterministically ----
    if (tau == 0) {
        __threadfence();
        int d = atomicAdd(&g_done, 1);
        sh_last = (d == (Bn / 2 - 1));
    }
    __syncthreads();
    if (sh_last) {
        __threadfence();                 // see all CTAs' g_partial writes
        float v = g_partial[tau];        // fixed-tree: deterministic
        #pragma unroll
        for (int o = 16; o; o >>= 1) v += __shfl_xor_sync(0xffffffffu, v, o);
        if (lane == 0) sh_wred[warp] = v;
        __syncthreads();
        if (tau == 0) {
            float s = ((sh_wred[0] + sh_wred[1]) + (sh_wred[2] + sh_wred[3]))
                    + ((sh_wred[4] + sh_wred[5]) + (sh_wred[6] + sh_wred[7]));
            out[0]  = s;
            g_done  = 0;                 // reset for next graph replay
        }
    }
}

extern "C" void kernel_launch(void* const* d_in, const int* in_sizes, int n_in,
                              void* d_out, int out_size)
{
    const float* logits   = (const float*)d_in[0];
    const int*   labels   = (const int*)  d_in[1];
    const int*   seq_lens = (const int*)  d_in[2];
    const float* trans    = (const float*)d_in[3];
    float*       out      = (float*)d_out;

    crf_sched_kernel<<<32, 256>>>(seq_lens);
    crf_forward_kernel<<<Bn / 2, 256>>>(logits, labels, seq_lens, trans, out);
}